// round 12
// baseline (speedup 1.0000x reference)
#include <cuda_runtime.h>
#include <math.h>

#define NG 512
#define NSEG 4
#define SEGSZ 128
#define IMG_H 256
#define IMG_W 256
#define NPIX (IMG_H * IMG_W)
#define NTILE 256               // 8 x 32 tiles of 32x8 px
#define EPSV 1e-4f
#define CUT 50.0f

#define NBLK_PROJ 128
#define NBLK_REND 1024          // 8 x 32 tiles x 4 segments
#define NBLK_TOT  (NBLK_PROJ + NBLK_REND)

// Sorted-by-depth gaussian params:
//  g_cull[r] = (mx, my, rx, ry)   conservative ellipse AABB half-extents
//  g_p0[r]   = (mx, my, ia, ib)   mean + inverse-cov entries
//  g_p1[r]   = (id, coeff, colR, colG)
//  g_cb[r]   = colB
__device__ float4 g_cull[NG];
__device__ float4 g_p0[NG];
__device__ float4 g_p1[NG];
__device__ float  g_cb[NG];
// Per-segment partial composites: (R, G, B, T) per pixel, segment-major.
__device__ float4 g_seg[NSEG * NPIX];
// Sync state. All counters return to 0 before the kernel ends (replay-safe):
//  g_flag1: projection-done counter (0 -> 128; reset by last merged tile)
//  g_done:  per-tile arrival counters (0 -> 4; reset by that tile's merger)
//  g_fin:   merged-tile counter (0 -> 256; self-resets)
__device__ int g_flag1;
__device__ int g_done[NTILE];
__device__ int g_fin;

__device__ __forceinline__ int acq_load(const int* p) {
    int v;
    asm volatile("ld.acquire.gpu.b32 %0, [%1];" : "=r"(v) : "l"(p) : "memory");
    return v;
}

// ---------------------------------------------------------------------------
// Fused kernel: 1152 blocks x 128 threads, all co-resident:
// launch_bounds(128, 8) -> <=64 regs -> 8 blocks/SM -> 1184 slots >= 1152,
// static smem ~9 KB/block (<= 28.5 KB budget), so every block is in wave 1
// and the flag1 spin cannot deadlock. No global barrier exists: merge is
// gated per-tile by a 4-arrival counter (validated in R11).
//   blocks [0,128):     projection + stable depth sort (1 warp / gaussian)
//   blocks [128,1152):  per-(tile,segment) cull + composite + per-tile merge
// ---------------------------------------------------------------------------
__global__ void __launch_bounds__(128, 8) fused_kernel(
        const float* __restrict__ means3D,
        const float* __restrict__ covs3d,
        const float* __restrict__ colors,
        const float* __restrict__ opac,
        const float* __restrict__ Km,
        const float* __restrict__ Rm,
        const float* __restrict__ tv,
        float* __restrict__ out) {
    __shared__ __align__(16) unsigned long long skey[NG];   // projection path
    __shared__ float4 sG1[SEGSZ];                            // render path
    __shared__ float4 sG2[SEGSZ];
    __shared__ float  sCB[SEGSZ];
    __shared__ int segTot[4];
    __shared__ int segOff[4];
    __shared__ int sCount;
    __shared__ int sLast;

    int bid  = blockIdx.x;
    int tid  = threadIdx.x;
    int lane = tid & 31;
    int wrp  = tid >> 5;

    // ======================= PROJECTION BLOCKS =============================
    if (bid < NBLK_PROJ) {
        float R00=Rm[0],R01=Rm[1],R02=Rm[2];
        float R10=Rm[3],R11=Rm[4],R12=Rm[5];
        float R20=Rm[6],R21=Rm[7],R22=Rm[8];
        float tx0=tv[0], tx1=tv[1], tx2=tv[2];

        // phase A: all 512 depth keys (4 per thread).
        // depth >= 1 > 0 so float bit order == value order;
        // (depth_bits<<32 | idx) rank == stable jnp.argsort.
        #pragma unroll
        for (int k = 0; k < 4; k++) {
            int g = k * 128 + tid;
            float m0 = means3D[3*g], m1 = means3D[3*g+1], m2 = means3D[3*g+2];
            float cz = R20*m0 + R21*m1 + R22*m2 + tx2;
            float depth = fmaxf(cz, 1.0f);
            skey[g] = ((unsigned long long)__float_as_uint(depth) << 32) | (unsigned)g;
        }
        __syncthreads();

        // phase B: one warp per gaussian; all 32 lanes redundantly project
        // (issues the LDGs early so their latency overlaps the rank scan).
        int i = bid * 4 + wrp;

        float m0 = means3D[3*i], m1 = means3D[3*i+1], m2 = means3D[3*i+2];
        const float* C = covs3d + 9*i;
        float C0=C[0],C1=C[1],C2=C[2],C3=C[3],C4=C[4],C5=C[5],C6=C[6],C7=C[7],C8=C[8];
        float c0 = colors[3*i], c1 = colors[3*i+1], c2 = colors[3*i+2];
        float op = opac[i];

        float cx = R00*m0 + R01*m1 + R02*m2 + tx0;
        float cy = R10*m0 + R11*m1 + R12*m2 + tx1;
        float cz = R20*m0 + R21*m1 + R22*m2 + tx2;
        float z = cz;
        float depth = fmaxf(z, 1.0f);

        float K00=Km[0],K01=Km[1],K02=Km[2];
        float K10=Km[3],K11=Km[4],K12=Km[5];
        float K20=Km[6],K21=Km[7],K22=Km[8];

        float sx = K00*cx + K01*cy + K02*cz;
        float sy = K10*cx + K11*cy + K12*cz;
        float sz = K20*cx + K21*cy + K22*cz;
        float mx = sx / sz;
        float my = sy / sz;

        // C_cam = R C R^T ; need (0,0), (0,1), (1,1)
        float u0 = R00*C0 + R01*C3 + R02*C6;
        float u1 = R00*C1 + R01*C4 + R02*C7;
        float u2 = R00*C2 + R01*C5 + R02*C8;
        float v0 = R10*C0 + R11*C3 + R12*C6;
        float v1 = R10*C1 + R11*C4 + R12*C7;
        float v2 = R10*C2 + R11*C5 + R12*C8;
        float Cc00 = u0*R00 + u1*R01 + u2*R02;
        float Cc01 = u0*R10 + u1*R11 + u2*R12;
        float Cc11 = v0*R10 + v1*R11 + v2*R12;

        // only J[0,0]=fx/z, J[1,1]=fy/z survive the [:2,:2] slice of J^T C J
        float jx = K00 / z;
        float jy = K11 / z;
        float a = jx*jx*Cc00 + EPSV;
        float b = jx*jy*Cc01;
        float d = jy*jy*Cc11 + EPSV;

        float det    = a*d - b*b;
        float invdet = 1.0f / det;
        float ia =  d * invdet;
        float ib = -b * invdet;
        float id =  a * invdet;

        float norm  = 1.0f / (6.283185307179586f * sqrtf(det));
        bool  valid = (depth > 1.0f) && (depth < 50.0f);
        float coeff = valid ? (op * norm) : 0.0f;

        float rxv = valid ? sqrtf(CUT * a) : -1e30f;
        float ryv = valid ? sqrtf(CUT * d) : -1e30f;

        // warp-cooperative stable rank over ALL 512 keys:
        // 32 lanes x 8 uint4 = 256 uint4; sk4[j*32+lane] is conflict-free.
        unsigned long long ki = skey[i];
        const uint4* sk4 = (const uint4*)skey;
        int r = 0;
        #pragma unroll
        for (int j = 0; j < 8; j++) {
            uint4 v = sk4[j * 32 + lane];
            unsigned long long k0 = ((unsigned long long)v.y << 32) | v.x;
            unsigned long long k1 = ((unsigned long long)v.w << 32) | v.z;
            r += (int)(k0 < ki) + (int)(k1 < ki);
        }
        r = __reduce_add_sync(0xffffffffu, r);

        if (lane == 0) {
            g_cull[r] = make_float4(mx, my, rxv, ryv);
            g_p0[r]   = make_float4(mx, my, ia, ib);
            g_p1[r]   = make_float4(id, coeff, c0, c1);
            g_cb[r]   = c2;
        }
        __syncthreads();
        if (tid == 0) {
            __threadfence();                 // release g_* writes
            atomicAdd(&g_flag1, 1);
        }
        return;
    }

    // ========================= RENDER BLOCKS ===============================
    int rid  = bid - NBLK_PROJ;
    int seg  = rid >> 8;                 // 0..3
    int txi  = rid & 7;                  // tile x (0..7)
    int tyi  = (rid >> 3) & 31;          // tile y (0..31)
    int tile = tyi * 8 + txi;

    // wait for projection (moderate backoff: don't hammer the L2 line)
    if (tid == 0) {
        while (acq_load(&g_flag1) < NBLK_PROJ) __nanosleep(128);
    }
    __syncthreads();

    float x0 = (float)(txi * 32);
    float y0 = (float)(tyi * 8);
    float x1 = x0 + 31.0f;
    float y1 = y0 + 7.0f;

    // cull this segment's 128 gaussians against the tile AABB
    int g = seg * SEGSZ + tid;
    float4 c = g_cull[g];
    bool keep = (c.x + c.z >= x0) && (c.x - c.z <= x1) &&
                (c.y + c.w >= y0) && (c.y - c.w <= y1);
    unsigned mask = __ballot_sync(0xffffffffu, keep);
    if (lane == 0) segTot[wrp] = __popc(mask);
    __syncthreads();
    if (tid == 0) {
        int s = 0;
        #pragma unroll
        for (int w = 0; w < 4; w++) { segOff[w] = s; s += segTot[w]; }
        sCount = s;
    }
    __syncthreads();

    // order-preserving scatter into smem
    if (keep) {
        int pos = segOff[wrp] + __popc(mask & ((1u << lane) - 1u));
        sG1[pos] = g_p0[g];
        sG2[pos] = g_p1[g];
        sCB[pos] = g_cb[g];
    }
    __syncthreads();
    int count = sCount;

    int x  = txi * 32 + lane;
    int yA = tyi * 8 + wrp;
    int yB = yA + 4;
    int pixA = yA * IMG_W + x;
    int pixB = yB * IMG_W + x;

    float T0 = 1.0f, T1 = 1.0f;
    float aR0 = 0.f, aG0 = 0.f, aB0 = 0.f;
    float aR1 = 0.f, aG1 = 0.f, aB1 = 0.f;

    if (count > 0) {
        float px  = x0 + (float)lane;
        float py0 = y0 + (float)wrp;
        float py1 = py0 + 4.0f;

        // software-pipelined loop: prefetch i+1 while compositing i
        float4 p0 = sG1[0], p1 = sG2[0];
        float  cb = sCB[0];
        int last = count - 1;

        for (int i = 0; i < count; i++) {
            int j = min(i + 1, last);
            float4 n0 = sG1[j];
            float4 n1 = sG2[j];
            float  ncb = sCB[j];

            float dx  = px  - p0.x;
            float dy0 = py0 - p0.y;
            float dy1 = py1 - p0.y;
            float tx  = fmaf(p0.z, dx, p0.w * dy0);
            float ty  = fmaf(p0.w, dx, p1.x * dy0);
            float m0  = fmaf(tx, dx, ty * dy0);
            float ux  = fmaf(p0.z, dx, p0.w * dy1);
            float uy  = fmaf(p0.w, dx, p1.x * dy1);
            float m1  = fmaf(ux, dx, uy * dy1);

            if (fminf(m0, m1) < CUT) {
                float e0 = p1.y * __expf(-0.5f * m0);
                float e1 = p1.y * __expf(-0.5f * m1);
                float w0 = e0 * T0;
                float w1 = e1 * T1;
                aR0 = fmaf(w0, p1.z, aR0);
                aG0 = fmaf(w0, p1.w, aG0);
                aB0 = fmaf(w0, cb,   aB0);
                aR1 = fmaf(w1, p1.z, aR1);
                aG1 = fmaf(w1, p1.w, aG1);
                aB1 = fmaf(w1, cb,   aB1);
                T0 -= w0;
                T1 -= w1;
            }

            p0 = n0; p1 = n1; cb = ncb;
        }
    }

    // publish this segment's partial
    g_seg[seg * NPIX + pixA] = make_float4(aR0, aG0, aB0, T0);
    g_seg[seg * NPIX + pixB] = make_float4(aR1, aG1, aB1, T1);

    // arrive at the tile counter; 4th block merges
    __threadfence();          // release partials
    __syncthreads();          // all threads' stores included before arrive
    if (tid == 0) sLast = (atomicAdd(&g_done[tile], 1) == NSEG - 1);
    __syncthreads();
    if (!sLast) return;
    __threadfence();          // acquire other blocks' partials

    // merge: out = c0 + T0*(c1 + T1*(c2 + T2*c3)); own segment from registers.
    float4 own0 = make_float4(aR0, aG0, aB0, T0);
    float4 own1 = make_float4(aR1, aG1, aB1, T1);

    #pragma unroll
    for (int h = 0; h < 2; h++) {
        int pix = h ? pixB : pixA;
        float4 own = h ? own1 : own0;

        float4 s0 = (seg == 0) ? own : g_seg[pix];
        float4 s1 = (seg == 1) ? own : g_seg[pix + NPIX];
        float4 s2 = (seg == 2) ? own : g_seg[pix + 2 * NPIX];
        float4 s3 = (seg == 3) ? own : g_seg[pix + 3 * NPIX];

        float R = fmaf(s2.w, s3.x, s2.x);
        float G = fmaf(s2.w, s3.y, s2.y);
        float B = fmaf(s2.w, s3.z, s2.z);
        R = fmaf(s1.w, R, s1.x);
        G = fmaf(s1.w, G, s1.y);
        B = fmaf(s1.w, B, s1.z);
        R = fmaf(s0.w, R, s0.x);
        G = fmaf(s0.w, G, s0.y);
        B = fmaf(s0.w, B, s0.z);

        int o = pix * 3;
        out[o + 0] = R;
        out[o + 1] = G;
        out[o + 2] = B;
    }

    __syncthreads();
    if (tid == 0) {
        g_done[tile] = 0;                 // per-tile reset (replay-safe)
        int v = atomicAdd(&g_fin, 1);
        if (v == NTILE - 1) {
            // Last merged tile: every render block has passed the flag1
            // spin (all 1024 must composite before all 256 tiles merge),
            // so resetting flag1 here cannot strand a spinner.
            g_flag1 = 0;
            __threadfence();
            g_fin = 0;
        }
    }
}

extern "C" void kernel_launch(void* const* d_in, const int* in_sizes, int n_in,
                              void* d_out, int out_size) {
    const float* means3D   = (const float*)d_in[0];
    const float* covs3d    = (const float*)d_in[1];
    const float* colors    = (const float*)d_in[2];
    const float* opacities = (const float*)d_in[3];
    const float* K         = (const float*)d_in[4];
    const float* R         = (const float*)d_in[5];
    const float* t         = (const float*)d_in[6];
    float* out = (float*)d_out;

    fused_kernel<<<NBLK_TOT, 128>>>(means3D, covs3d, colors, opacities,
                                    K, R, t, out);
}

// round 13
// speedup vs baseline: 1.0408x; 1.0408x over previous
#include <cuda_runtime.h>
#include <math.h>

#define NG 512
#define NSEG 4
#define SEGSZ 128
#define IMG_H 256
#define IMG_W 256
#define NPIX (IMG_H * IMG_W)
#define NTILE 256               // 8 x 32 tiles of 32x8 px
#define EPSV 1e-4f
#define CUT 40.0f

#define NBLK_PROJ 128
#define NBLK_REND 1024          // 8 x 32 tiles x 4 segments
#define NBLK_TOT  (NBLK_PROJ + NBLK_REND)
#define NREADY 64               // fan-out release lines

// Sorted-by-depth gaussian params:
//  g_cull[r] = (mx, my, rx, ry)   conservative ellipse AABB half-extents
//  g_p0[r]   = (mx, my, ia, ib)   mean + inverse-cov entries
//  g_p1[r]   = (id, coeff, colR, colG)
//  g_cb[r]   = colB
__device__ float4 g_cull[NG];
__device__ float4 g_p0[NG];
__device__ float4 g_p1[NG];
__device__ float  g_cb[NG];
// Per-segment partial composites: (R, G, B, T) per pixel, segment-major.
__device__ float4 g_seg[NSEG * NPIX];
// Sync state. Everything returns to 0 before kernel end (graph-replay safe):
//  g_flag1: projection-done counter (0 -> 128)
//  g_ready: 64 fan-out release lines (0 -> 1), polled by render blocks
//  g_done:  per-tile arrival counters (0 -> 4)
//  g_fin:   merged-tile counter (0 -> 256)
__device__ int g_flag1;
__device__ int g_ready[NREADY];
__device__ int g_done[NTILE];
__device__ int g_fin;

__device__ __forceinline__ int acq_load(const int* p) {
    int v;
    asm volatile("ld.acquire.gpu.b32 %0, [%1];" : "=r"(v) : "l"(p) : "memory");
    return v;
}

// ---------------------------------------------------------------------------
// Fused kernel: 1152 blocks x 128 threads, all co-resident:
// launch_bounds(128, 8) -> <=64 regs -> 8 blocks/SM -> 1184 slots >= 1152,
// static smem ~9 KB/block, so every block lands in wave 1 and the ready-line
// spin cannot deadlock. No global barrier: merge is per-tile (4 arrivals).
//   blocks [0,128):     projection + stable depth sort (1 warp / gaussian)
//   blocks [128,1152):  per-(tile,segment) cull + composite + per-tile merge
// Release is fanned out over 64 lines so 1024 pollers never contend on one
// L2 line (the R12 spin storm: ~5 loads/ns against ~1.8/ns LTS service).
// ---------------------------------------------------------------------------
__global__ void __launch_bounds__(128, 8) fused_kernel(
        const float* __restrict__ means3D,
        const float* __restrict__ covs3d,
        const float* __restrict__ colors,
        const float* __restrict__ opac,
        const float* __restrict__ Km,
        const float* __restrict__ Rm,
        const float* __restrict__ tv,
        float* __restrict__ out) {
    __shared__ __align__(16) unsigned long long skey[NG];   // projection path
    __shared__ float4 sG1[SEGSZ + 1];                        // render path
    __shared__ float4 sG2[SEGSZ + 1];                        // (+1 = sentinel)
    __shared__ float  sCB[SEGSZ + 1];
    __shared__ int segTot[4];
    __shared__ int segOff[4];
    __shared__ int sCount;
    __shared__ int sLast;

    int bid  = blockIdx.x;
    int tid  = threadIdx.x;
    int lane = tid & 31;
    int wrp  = tid >> 5;

    // ======================= PROJECTION BLOCKS =============================
    if (bid < NBLK_PROJ) {
        float R00=Rm[0],R01=Rm[1],R02=Rm[2];
        float R10=Rm[3],R11=Rm[4],R12=Rm[5];
        float R20=Rm[6],R21=Rm[7],R22=Rm[8];
        float tx0=tv[0], tx1=tv[1], tx2=tv[2];

        // phase A: all 512 depth keys (4 per thread).
        // depth >= 1 > 0 so float bit order == value order;
        // (depth_bits<<32 | idx) rank == stable jnp.argsort.
        #pragma unroll
        for (int k = 0; k < 4; k++) {
            int g = k * 128 + tid;
            float m0 = means3D[3*g], m1 = means3D[3*g+1], m2 = means3D[3*g+2];
            float cz = R20*m0 + R21*m1 + R22*m2 + tx2;
            float depth = fmaxf(cz, 1.0f);
            skey[g] = ((unsigned long long)__float_as_uint(depth) << 32) | (unsigned)g;
        }
        __syncthreads();

        // phase B: one warp per gaussian; all 32 lanes redundantly project
        // (issues the LDGs early so their latency overlaps the rank scan).
        int i = bid * 4 + wrp;

        float m0 = means3D[3*i], m1 = means3D[3*i+1], m2 = means3D[3*i+2];
        const float* C = covs3d + 9*i;
        float C0=C[0],C1=C[1],C2=C[2],C3=C[3],C4=C[4],C5=C[5],C6=C[6],C7=C[7],C8=C[8];
        float c0 = colors[3*i], c1 = colors[3*i+1], c2 = colors[3*i+2];
        float op = opac[i];

        float cx = R00*m0 + R01*m1 + R02*m2 + tx0;
        float cy = R10*m0 + R11*m1 + R12*m2 + tx1;
        float cz = R20*m0 + R21*m1 + R22*m2 + tx2;
        float z = cz;
        float depth = fmaxf(z, 1.0f);

        float K00=Km[0],K01=Km[1],K02=Km[2];
        float K10=Km[3],K11=Km[4],K12=Km[5];
        float K20=Km[6],K21=Km[7],K22=Km[8];

        float sx = K00*cx + K01*cy + K02*cz;
        float sy = K10*cx + K11*cy + K12*cz;
        float sz = K20*cx + K21*cy + K22*cz;
        float mx = sx / sz;
        float my = sy / sz;

        // C_cam = R C R^T ; need (0,0), (0,1), (1,1)
        float u0 = R00*C0 + R01*C3 + R02*C6;
        float u1 = R00*C1 + R01*C4 + R02*C7;
        float u2 = R00*C2 + R01*C5 + R02*C8;
        float v0 = R10*C0 + R11*C3 + R12*C6;
        float v1 = R10*C1 + R11*C4 + R12*C7;
        float v2 = R10*C2 + R11*C5 + R12*C8;
        float Cc00 = u0*R00 + u1*R01 + u2*R02;
        float Cc01 = u0*R10 + u1*R11 + u2*R12;
        float Cc11 = v0*R10 + v1*R11 + v2*R12;

        // only J[0,0]=fx/z, J[1,1]=fy/z survive the [:2,:2] slice of J^T C J
        float jx = K00 / z;
        float jy = K11 / z;
        float a = jx*jx*Cc00 + EPSV;
        float b = jx*jy*Cc01;
        float d = jy*jy*Cc11 + EPSV;

        float det    = a*d - b*b;
        float invdet = 1.0f / det;
        float ia =  d * invdet;
        float ib = -b * invdet;
        float id =  a * invdet;

        float norm  = 1.0f / (6.283185307179586f * sqrtf(det));
        bool  valid = (depth > 1.0f) && (depth < 50.0f);
        float coeff = valid ? (op * norm) : 0.0f;

        float rxv = valid ? sqrtf(CUT * a) : -1e30f;
        float ryv = valid ? sqrtf(CUT * d) : -1e30f;

        // warp-cooperative stable rank over ALL 512 keys:
        // 32 lanes x 8 uint4 = 256 uint4; sk4[j*32+lane] is conflict-free.
        unsigned long long ki = skey[i];
        const uint4* sk4 = (const uint4*)skey;
        int r = 0;
        #pragma unroll
        for (int j = 0; j < 8; j++) {
            uint4 v = sk4[j * 32 + lane];
            unsigned long long k0 = ((unsigned long long)v.y << 32) | v.x;
            unsigned long long k1 = ((unsigned long long)v.w << 32) | v.z;
            r += (int)(k0 < ki) + (int)(k1 < ki);
        }
        r = __reduce_add_sync(0xffffffffu, r);

        if (lane == 0) {
            g_cull[r] = make_float4(mx, my, rxv, ryv);
            g_p0[r]   = make_float4(mx, my, ia, ib);
            g_p1[r]   = make_float4(id, coeff, c0, c1);
            g_cb[r]   = c2;
        }
        __syncthreads();
        if (tid == 0) {
            __threadfence();                 // release g_* writes
            sLast = (atomicAdd(&g_flag1, 1) == NBLK_PROJ - 1);
        }
        __syncthreads();
        if (sLast) {
            // fan-out release: 64 independent lines, one per poll group
            __threadfence();
            if (tid < NREADY) atomicExch(&g_ready[tid], 1);
        }
        return;
    }

    // ========================= RENDER BLOCKS ===============================
    int rid  = bid - NBLK_PROJ;
    int seg  = rid >> 8;                 // 0..3
    int txi  = rid & 7;                  // tile x (0..7)
    int tyi  = (rid >> 3) & 31;          // tile y (0..31)
    int tile = tyi * 8 + txi;

    // wait for projection on this block's ready line (16 pollers per line)
    if (tid == 0) {
        while (acq_load(&g_ready[rid & (NREADY - 1)]) == 0) __nanosleep(100);
    }
    __syncthreads();

    float x0 = (float)(txi * 32);
    float y0 = (float)(tyi * 8);
    float x1 = x0 + 31.0f;
    float y1 = y0 + 7.0f;

    // cull this segment's 128 gaussians against the tile AABB
    int g = seg * SEGSZ + tid;
    float4 c = g_cull[g];
    bool keep = (c.x + c.z >= x0) && (c.x - c.z <= x1) &&
                (c.y + c.w >= y0) && (c.y - c.w <= y1);
    unsigned mask = __ballot_sync(0xffffffffu, keep);
    if (lane == 0) segTot[wrp] = __popc(mask);
    __syncthreads();
    if (tid == 0) {
        int s = 0;
        #pragma unroll
        for (int w = 0; w < 4; w++) { segOff[w] = s; s += segTot[w]; }
        sCount = s;
        // sentinel: far-away mean, zero coeff -> never hits, kills the clamp
        sG1[s] = make_float4(1e30f, 1e30f, 1.0f, 0.0f);
        sG2[s] = make_float4(1.0f, 0.0f, 0.0f, 0.0f);
        sCB[s] = 0.0f;
    }
    __syncthreads();

    // order-preserving scatter into smem
    if (keep) {
        int pos = segOff[wrp] + __popc(mask & ((1u << lane) - 1u));
        sG1[pos] = g_p0[g];
        sG2[pos] = g_p1[g];
        sCB[pos] = g_cb[g];
    }
    __syncthreads();
    int count = sCount;

    int x  = txi * 32 + lane;
    int yA = tyi * 8 + wrp;
    int yB = yA + 4;
    int pixA = yA * IMG_W + x;
    int pixB = yB * IMG_W + x;

    float T0 = 1.0f, T1 = 1.0f;
    float aR0 = 0.f, aG0 = 0.f, aB0 = 0.f;
    float aR1 = 0.f, aG1 = 0.f, aB1 = 0.f;

    if (count > 0) {
        float px  = x0 + (float)lane;
        float py0 = y0 + (float)wrp;
        float py1 = py0 + 4.0f;

        // software-pipelined loop: prefetch i+1 (sentinel-padded, no clamp)
        float4 p0 = sG1[0], p1 = sG2[0];
        float  cb = sCB[0];

        for (int i = 0; i < count; i++) {
            float4 n0 = sG1[i + 1];
            float4 n1 = sG2[i + 1];
            float  ncb = sCB[i + 1];

            float dx  = px  - p0.x;
            float dy0 = py0 - p0.y;
            float dy1 = py1 - p0.y;
            float tx  = fmaf(p0.z, dx, p0.w * dy0);
            float ty  = fmaf(p0.w, dx, p1.x * dy0);
            float m0  = fmaf(tx, dx, ty * dy0);
            float ux  = fmaf(p0.z, dx, p0.w * dy1);
            float uy  = fmaf(p0.w, dx, p1.x * dy1);
            float m1  = fmaf(ux, dx, uy * dy1);

            if (fminf(m0, m1) < CUT) {
                float e0 = p1.y * __expf(-0.5f * m0);
                float e1 = p1.y * __expf(-0.5f * m1);
                float w0 = e0 * T0;
                float w1 = e1 * T1;
                aR0 = fmaf(w0, p1.z, aR0);
                aG0 = fmaf(w0, p1.w, aG0);
                aB0 = fmaf(w0, cb,   aB0);
                aR1 = fmaf(w1, p1.z, aR1);
                aG1 = fmaf(w1, p1.w, aG1);
                aB1 = fmaf(w1, cb,   aB1);
                T0 -= w0;
                T1 -= w1;
            }

            p0 = n0; p1 = n1; cb = ncb;
        }
    }

    // publish this segment's partial
    g_seg[seg * NPIX + pixA] = make_float4(aR0, aG0, aB0, T0);
    g_seg[seg * NPIX + pixB] = make_float4(aR1, aG1, aB1, T1);

    // arrive at the tile counter; 4th block merges
    __threadfence();          // release partials
    __syncthreads();          // all threads' stores included before arrive
    if (tid == 0) sLast = (atomicAdd(&g_done[tile], 1) == NSEG - 1);
    __syncthreads();
    if (!sLast) return;
    __threadfence();          // acquire other blocks' partials

    // merge: out = c0 + T0*(c1 + T1*(c2 + T2*c3)); own segment from registers.
    float4 own0 = make_float4(aR0, aG0, aB0, T0);
    float4 own1 = make_float4(aR1, aG1, aB1, T1);

    #pragma unroll
    for (int h = 0; h < 2; h++) {
        int pix = h ? pixB : pixA;
        float4 own = h ? own1 : own0;

        float4 s0 = (seg == 0) ? own : g_seg[pix];
        float4 s1 = (seg == 1) ? own : g_seg[pix + NPIX];
        float4 s2 = (seg == 2) ? own : g_seg[pix + 2 * NPIX];
        float4 s3 = (seg == 3) ? own : g_seg[pix + 3 * NPIX];

        float R = fmaf(s2.w, s3.x, s2.x);
        float G = fmaf(s2.w, s3.y, s2.y);
        float B = fmaf(s2.w, s3.z, s2.z);
        R = fmaf(s1.w, R, s1.x);
        G = fmaf(s1.w, G, s1.y);
        B = fmaf(s1.w, B, s1.z);
        R = fmaf(s0.w, R, s0.x);
        G = fmaf(s0.w, G, s0.y);
        B = fmaf(s0.w, B, s0.z);

        int o = pix * 3;
        out[o + 0] = R;
        out[o + 1] = G;
        out[o + 2] = B;
    }

    // reset all sync state for the next graph replay.
    // Safe: the 256th merged tile implies all 1024 render blocks have passed
    // the ready-line spin, so nobody can still be polling g_ready/g_flag1.
    __syncthreads();
    if (tid == 0) {
        g_done[tile] = 0;
        sLast = (atomicAdd(&g_fin, 1) == NTILE - 1);
    }
    __syncthreads();
    if (sLast) {
        if (tid < NREADY) g_ready[tid] = 0;
        if (tid == 0) {
            g_flag1 = 0;
            __threadfence();
            g_fin = 0;
        }
    }
}

extern "C" void kernel_launch(void* const* d_in, const int* in_sizes, int n_in,
                              void* d_out, int out_size) {
    const float* means3D   = (const float*)d_in[0];
    const float* covs3d    = (const float*)d_in[1];
    const float* colors    = (const float*)d_in[2];
    const float* opacities = (const float*)d_in[3];
    const float* K         = (const float*)d_in[4];
    const float* R         = (const float*)d_in[5];
    const float* t         = (const float*)d_in[6];
    float* out = (float*)d_out;

    fused_kernel<<<NBLK_TOT, 128>>>(means3D, covs3d, colors, opacities,
                                    K, R, t, out);
}